// round 17
// baseline (speedup 1.0000x reference)
#include <cuda_runtime.h>

// plane_rotations — CONVERGED OPTIMUM (held; 16 rounds).
// dur across 11 runs of this exact binary:
//   {23.008 x4, 23.040 x3, 23.264 x2, 22.976, 22.720} us
//   mean 23.06, sigma ~0.15 — DVFS noise band around the floor. The 22.72
//   sample is a one-off favorable clock draw on unchanged bytes.
//
// Math: the reference's scan rebuilds the matrix from ZEROS each step (only
// rows i,j are written). The nonzero-row support collapses: after the (0,k)
// chain the support is {0,127}; step (1,2) reads two all-zero rows and yields
// the zero matrix (exact in fp32: c*0 - s*0 = 0), which persists through all
// remaining ~8000 steps. Hence out = x @ 0^T = 0 exactly, for any inputs.
// The problem reduces to zero-filling the 128 MiB output.
//
// All optimization branches measured closed:
//  - Work: one 134.2MB store pass is mandatory (d_out poisoned pre-timing).
//  - Bandwidth: STG.128 / STG.CS / L2-pin split / STG.WT / createpolicy
//    evict_last / driver memset all at 6.45 TB/s = path-independent LTS store
//    cap (~6300 B/cyc). evict_last moved DRAM 45%->41% with 0.000us runtime
//    change => LTS binds; cache-policy and TMA branches closed.
//  - Concurrency: second node shares the one LTS -> net negative.
//  - Graph: single memset node = min count x cheapest type (-1.7us vs kernel).

extern "C" void kernel_launch(void* const* d_in, const int* in_sizes, int n_in,
                              void* d_out, int out_size) {
    (void)d_in; (void)in_sizes; (void)n_in;
    cudaMemsetAsync(d_out, 0, (size_t)out_size * sizeof(float));
}